// round 14
// baseline (speedup 1.0000x reference)
#include <cuda_runtime.h>

// Tiny-ViT fused forward, round 12: REVERT to R8 (201.5us best: de-dup fp32
// weights + repack movs, head-split attention, syncwarp) + algebraic folds:
//  - LN gains folded into Wq/Wk/Wv/W1 at staging (LN apply-step deleted)
//  - LN betas + biases folded into dot-chain inits (bias adds deleted)
//  - softmax scale*log2e folded into Wq'
// CTA: 256 threads = 8 warps = 8 slots = 16 images. grid = B/16.

namespace {
constexpr int NB  = 4;
constexpr int TT  = 50;
constexpr int NTH = 256;
constexpr int WPC = 8;
constexpr int IPC = 16;
constexpr int ROW  = 18;   // u64 per kv token row (144B)
constexpr int VOFF = 10;
constexpr int KV_U64 = WPC * TT * ROW;        // 7200
constexpr int ST_STR = 18;
constexpr int ST_U64 = WPC * 25 * ST_STR;     // 3600

struct SW {  // de-duplicated fp32 weights (R8 layout) with folded variants
  float Wq[NB * 64], Wk[NB * 64], Wv[NB * 64], projW[NB * 64];  // gains folded
  float W1[NB * 256], W2t[NB * 256];                            // W1: g2 folded
  float qb[NB * 8], kb[NB * 8], vb[NB * 8];   // beta-fold bias vectors
  float b1e[NB * 32];                          // b1 + W1·b2ln
  float projb[NB * 8], b2[NB * 8];
  float linW[128];
  float cls[8];
  float pos[TT * 8];
  float mlpW[80], mlpb[12];
};
}  // namespace

typedef unsigned long long u64;

__device__ __forceinline__ u64 pk2(float a, float b) {
  u64 r;
  asm("mov.b64 %0, {%1, %2};" : "=l"(r)
      : "r"(__float_as_uint(a)), "r"(__float_as_uint(b)));
  return r;
}
__device__ __forceinline__ u64 pk1(float a) {
  u64 r;
  asm("mov.b64 %0, {%1, %1};" : "=l"(r) : "r"(__float_as_uint(a)));
  return r;
}
__device__ __forceinline__ void upk2(u64 v, float& a, float& b) {
  unsigned int x, y;
  asm("mov.b64 {%0, %1}, %2;" : "=r"(x), "=r"(y) : "l"(v));
  a = __uint_as_float(x); b = __uint_as_float(y);
}
__device__ __forceinline__ u64 fma2(u64 a, u64 b, u64 c) {
  u64 d;
  asm("fma.rn.f32x2 %0, %1, %2, %3;" : "=l"(d) : "l"(a), "l"(b), "l"(c));
  return d;
}
__device__ __forceinline__ u64 add2(u64 a, u64 b) {
  u64 d;
  asm("add.rn.f32x2 %0, %1, %2;" : "=l"(d) : "l"(a), "l"(b));
  return d;
}
__device__ __forceinline__ u64 mul2(u64 a, u64 b) {
  u64 d;
  asm("mul.rn.f32x2 %0, %1, %2;" : "=l"(d) : "l"(a), "l"(b));
  return d;
}
__device__ __forceinline__ float ex2f(float x) {
  float r;
  asm("ex2.approx.ftz.f32 %0, %1;" : "=f"(r) : "f"(x));
  return r;
}

// load 8-float row (2x LDS.128 broadcast) and pack to {w,w} dup pairs
__device__ __forceinline__ void ldrow8pk(const float* __restrict__ w, u64 wd[8]) {
  float4 w0 = *reinterpret_cast<const float4*>(w);
  float4 w1 = *reinterpret_cast<const float4*>(w + 4);
  wd[0] = pk1(w0.x); wd[1] = pk1(w0.y); wd[2] = pk1(w0.z); wd[3] = pk1(w0.w);
  wd[4] = pk1(w1.x); wd[5] = pk1(w1.y); wd[6] = pk1(w1.z); wd[7] = pk1(w1.w);
}

// dot8 with chain-init (bias folded in for free)
__device__ __forceinline__ u64 dot8ri(const u64 wd[8], const u64 h[8], u64 init) {
  u64 s0 = fma2(h[0], wd[0], init);
  u64 s1 = mul2(h[1], wd[1]);
  s0 = fma2(h[2], wd[2], s0); s1 = fma2(h[3], wd[3], s1);
  s0 = fma2(h[4], wd[4], s0); s1 = fma2(h[5], wd[5], s1);
  s0 = fma2(h[6], wd[6], s0); s1 = fma2(h[7], wd[7], s1);
  return add2(s0, s1);
}

// centered-scaled LN core: cs = (x - mu) * rsqrt(var + eps). gains/betas folded
// into downstream weights/biases at staging time.
__device__ __forceinline__ void cspack(const u64 x[8], u64 cs[8]) {
  u64 s = add2(add2(add2(x[0], x[1]), add2(x[2], x[3])),
               add2(add2(x[4], x[5]), add2(x[6], x[7])));
  float sA, sB;
  upk2(s, sA, sB);
  u64 mu = pk2(sA * 0.125f, sB * 0.125f);
  const u64 N1 = pk1(-1.f);
  u64 c[8];
#pragma unroll
  for (int d = 0; d < 8; d++) c[d] = fma2(mu, N1, x[d]);
  u64 v0 = mul2(c[0], c[0]);
  u64 v1 = mul2(c[1], c[1]);
  v0 = fma2(c[2], c[2], v0); v1 = fma2(c[3], c[3], v1);
  v0 = fma2(c[4], c[4], v0); v1 = fma2(c[5], c[5], v1);
  v0 = fma2(c[6], c[6], v0); v1 = fma2(c[7], c[7], v1);
  float vA, vB;
  upk2(add2(v0, v1), vA, vB);
  u64 rs = pk2(rsqrtf(fmaf(vA, 0.125f, 1e-5f)),
               rsqrtf(fmaf(vB, 0.125f, 1e-5f)));
#pragma unroll
  for (int d = 0; d < 8; d++) cs[d] = mul2(c[d], rs);
}

__global__ void __launch_bounds__(NTH, 2) vit_kernel(
    const float* __restrict__ images, const float* __restrict__ cls_g,
    const float* __restrict__ linW_g, const float* __restrict__ ln1g_g,
    const float* __restrict__ ln1b_g, const float* __restrict__ Wq_g,
    const float* __restrict__ Wk_g, const float* __restrict__ Wv_g,
    const float* __restrict__ projW_g, const float* __restrict__ projb_g,
    const float* __restrict__ ln2g_g, const float* __restrict__ ln2b_g,
    const float* __restrict__ W1_g, const float* __restrict__ b1_g,
    const float* __restrict__ W2_g, const float* __restrict__ b2_g,
    const float* __restrict__ mlpW_g, const float* __restrict__ mlpb_g,
    float* __restrict__ out, int B) {
  extern __shared__ __align__(16) char dsm[];
  u64* skv   = reinterpret_cast<u64*>(dsm);
  u64* stash = skv + KV_U64;
  SW* sw = reinterpret_cast<SW*>(reinterpret_cast<char*>(stash + ST_U64));

  const int tid = threadIdx.x;
  const float SCL2E = 0.35355339059327373f * 1.4426950408889634f;

  // ---- stage weights with folds ----
  {
    // Wq' = Wq * g1 * SCL2E ; Wk' = Wk*g1 ; Wv' = Wv*g1 ; W1' = W1*g2
    for (int i = tid; i < NB * 64; i += NTH) {
      int blk = i >> 6, d = i & 7;
      float g1 = ln1g_g[blk * 8 + d];
      sw->Wq[i] = Wq_g[i] * g1 * SCL2E;
      sw->Wk[i] = Wk_g[i] * g1;
      sw->Wv[i] = Wv_g[i] * g1;
      sw->projW[i] = projW_g[i];
    }
    for (int i = tid; i < NB * 256; i += NTH) {
      int blk = i >> 8, d = i & 7;
      sw->W1[i] = W1_g[i] * ln2g_g[blk * 8 + d];
      // W2 [blk][8][32] -> transposed [blk][32][8]
      int rem = i & 255, f = rem >> 3, dd = rem & 7;
      sw->W2t[blk * 256 + rem] = W2_g[blk * 256 + dd * 32 + f];
    }
    // beta-fold bias vectors: qb = SCL2E*Wq·b1ln ; kb = Wk·b1ln ; vb = Wv·b1ln
    for (int i = tid; i < NB * 8; i += NTH) {
      int blk = i >> 3, e = i & 7;
      const float* bb = ln1b_g + blk * 8;
      float sq = 0.f, sk = 0.f, sv = 0.f;
      for (int d = 0; d < 8; d++) {
        float bv = bb[d];
        sq += Wq_g[blk * 64 + e * 8 + d] * bv;
        sk += Wk_g[blk * 64 + e * 8 + d] * bv;
        sv += Wv_g[blk * 64 + e * 8 + d] * bv;
      }
      sw->qb[i] = sq * SCL2E;
      sw->kb[i] = sk;
      sw->vb[i] = sv;
      sw->projb[i] = projb_g[i];
      sw->b2[i] = b2_g[i];
    }
    // b1e = b1 + W1·b2ln
    for (int i = tid; i < NB * 32; i += NTH) {
      int blk = i >> 5, f = i & 31;
      const float* bb = ln2b_g + blk * 8;
      float s = b1_g[i];
      for (int d = 0; d < 8; d++) s += W1_g[blk * 256 + f * 8 + d] * bb[d];
      sw->b1e[i] = s;
    }
    auto cp = [&](float* d, const float* s, int n) {
      for (int i = tid; i < n; i += NTH) d[i] = s[i];
    };
    cp(sw->linW, linW_g, 128);
    cp(sw->cls, cls_g, 8);
    cp(sw->mlpW, mlpW_g, 80);
    for (int i = tid; i < 10; i += NTH) sw->mlpb[i] = mlpb_g[i];
    if (tid < TT) {  // sinusoidal table: freqs {1, .1, .01, .001}
      float tf = (float)tid;
      float* p = sw->pos + tid * 8;
      p[0] = sinf(tf);          p[1] = cosf(tf);
      p[2] = sinf(tf * 0.1f);   p[3] = cosf(tf * 0.1f);
      p[4] = sinf(tf * 0.01f);  p[5] = cosf(tf * 0.01f);
      p[6] = sinf(tf * 0.001f); p[7] = cosf(tf * 0.001f);
    }
  }
  __syncthreads();  // CTA-wide: weights staged cooperatively

  const int warp = tid >> 5;
  const int lane = tid & 31;
  const bool act = (lane < 25);
  const int t0 = lane;
  const int t1 = lane + 25;
  const int gb0 = (blockIdx.x * WPC + warp) * 2;
  const int gb1 = gb0 + 1;

  u64* kvb = skv + warp * (TT * ROW);
  u64* xs  = stash + (warp * 25 + lane) * ST_STR;

  u64 X0[8], X1[8];

  // ---- patch embed + positional ----
  if (act) {
    auto embed_tok = [&](int t, u64 xr[8]) {
      if (t == 0) {
#pragma unroll
        for (int d = 0; d < 8; d++) {
          float v = sw->cls[d] + sw->pos[d];
          xr[d] = pk1(v);
        }
        return;
      }
      int p = t - 1, r = p / 7, c = p % 7;
      float eo[2][8];
#pragma unroll
      for (int img = 0; img < 2; img++) {
        int gb = gb0 + img;
        float px[16];
        if (gb < B) {
          const float* ip = images + (size_t)gb * 784 + (r * 4) * 28 + c * 4;
#pragma unroll
          for (int i = 0; i < 4; i++) {
            float4 v4 = *reinterpret_cast<const float4*>(ip + i * 28);
            px[4 * i] = v4.x; px[4 * i + 1] = v4.y;
            px[4 * i + 2] = v4.z; px[4 * i + 3] = v4.w;
          }
        } else {
#pragma unroll
          for (int j = 0; j < 16; j++) px[j] = 0.f;
        }
#pragma unroll
        for (int d = 0; d < 8; d++) {
          const float* w = sw->linW + d * 16;
          float s = 0.f;
#pragma unroll
          for (int j = 0; j < 16; j++) s = fmaf(px[j], w[j], s);
          eo[img][d] = s + sw->pos[t * 8 + d];
        }
      }
#pragma unroll
      for (int d = 0; d < 8; d++) xr[d] = pk2(eo[0][d], eo[1][d]);
    };
    embed_tok(t0, X0);
    embed_tok(t1, X1);
  }

#pragma unroll 1
  for (int blk = 0; blk < NB; blk++) {
    u64 Q0[8], Q1[8];
    if (act) {
      // LN1 core (gains/betas folded downstream)
      u64 H0[8], H1[8];
      cspack(X0, H0);
      cspack(X1, H1);
      // stash X (dead until proj residual)
      {
        ulonglong2* s2 = reinterpret_cast<ulonglong2*>(xs);
#pragma unroll
        for (int i = 0; i < 4; i++)
          s2[i] = make_ulonglong2(X0[2 * i], X0[2 * i + 1]);
#pragma unroll
        for (int i = 0; i < 4; i++)
          s2[4 + i] = make_ulonglong2(X1[2 * i], X1[2 * i + 1]);
      }
      u64 wd[8], bp[8];
      const float* wq = sw->Wq + blk * 64;
      ldrow8pk(sw->qb + blk * 8, bp);
#pragma unroll
      for (int e = 0; e < 8; e++) {
        ldrow8pk(wq + e * 8, wd);
        Q0[e] = dot8ri(wd, H0, bp[e]);
        Q1[e] = dot8ri(wd, H1, bp[e]);
      }
      const float* wk = sw->Wk + blk * 64;
      ldrow8pk(sw->kb + blk * 8, bp);
      u64* kr0 = kvb + t0 * ROW;
      u64* kr1 = kvb + t1 * ROW;
#pragma unroll
      for (int e = 0; e < 8; e++) {
        ldrow8pk(wk + e * 8, wd);
        kr0[e] = dot8ri(wd, H0, bp[e]);
        kr1[e] = dot8ri(wd, H1, bp[e]);
      }
      const float* wv = sw->Wv + blk * 64;
      ldrow8pk(sw->vb + blk * 8, bp);
#pragma unroll
      for (int e = 0; e < 8; e++) {
        ldrow8pk(wv + e * 8, wd);
        kr0[VOFF + e] = dot8ri(wd, H0, bp[e]);
        kr1[VOFF + e] = dot8ri(wd, H1, bp[e]);
      }
    }
    __syncwarp();  // K/V warp-private

    u64 O0[8], O1[8];
    if (act) {
      // base-2 no-max softmax, two sequential per-head passes
#pragma unroll 1
      for (int h = 0; h < 2; h++) {
        const u64 q00 = Q0[4 * h + 0], q01 = Q0[4 * h + 1];
        const u64 q02 = Q0[4 * h + 2], q03 = Q0[4 * h + 3];
        const u64 q10 = Q1[4 * h + 0], q11 = Q1[4 * h + 1];
        const u64 q12 = Q1[4 * h + 2], q13 = Q1[4 * h + 3];
        const u64* kh = kvb + 4 * h;
        const u64* vh = kvb + VOFF + 4 * h;
        u64 l0 = 0, l1 = 0;
        u64 a00 = 0, a01 = 0, a02 = 0, a03 = 0;
        u64 a10 = 0, a11 = 0, a12 = 0, a13 = 0;
#pragma unroll 2
        for (int u = 0; u < TT; u++) {
          const ulonglong2* kp =
              reinterpret_cast<const ulonglong2*>(kh + u * ROW);
          ulonglong2 k0 = kp[0], k1 = kp[1];
          const ulonglong2* vp =
              reinterpret_cast<const ulonglong2*>(vh + u * ROW);
          ulonglong2 v0 = vp[0], v1 = vp[1];
          u64 s0 = fma2(q00, k0.x,
                   fma2(q01, k0.y, fma2(q02, k1.x, mul2(q03, k1.y))));
          u64 s1 = fma2(q10, k0.x,
                   fma2(q11, k0.y, fma2(q12, k1.x, mul2(q13, k1.y))));
          float xa, xb;
          upk2(s0, xa, xb);
          u64 p0 = pk2(ex2f(xa), ex2f(xb));
          upk2(s1, xa, xb);
          u64 p1 = pk2(ex2f(xa), ex2f(xb));
          l0 = add2(l0, p0);
          l1 = add2(l1, p1);
          a00 = fma2(p0, v0.x, a00); a01 = fma2(p0, v0.y, a01);
          a02 = fma2(p0, v1.x, a02); a03 = fma2(p0, v1.y, a03);
          a10 = fma2(p1, v0.x, a10); a11 = fma2(p1, v0.y, a11);
          a12 = fma2(p1, v1.x, a12); a13 = fma2(p1, v1.y, a13);
        }
        float lA, lB;
        upk2(l0, lA, lB);
        u64 i0 = pk2(1.f / lA, 1.f / lB);
        upk2(l1, lA, lB);
        u64 i1 = pk2(1.f / lA, 1.f / lB);
        O0[4 * h + 0] = mul2(a00, i0); O0[4 * h + 1] = mul2(a01, i0);
        O0[4 * h + 2] = mul2(a02, i0); O0[4 * h + 3] = mul2(a03, i0);
        O1[4 * h + 0] = mul2(a10, i1); O1[4 * h + 1] = mul2(a11, i1);
        O1[4 * h + 2] = mul2(a12, i1); O1[4 * h + 3] = mul2(a13, i1);
      }
    }
    __syncwarp();  // kv consumed

    if (act) {
      // reload X, proj + residual (proj bias via chain init)
      {
        const ulonglong2* s2 = reinterpret_cast<const ulonglong2*>(xs);
#pragma unroll
        for (int i = 0; i < 4; i++) {
          ulonglong2 v = s2[i];
          X0[2 * i] = v.x; X0[2 * i + 1] = v.y;
        }
#pragma unroll
        for (int i = 0; i < 4; i++) {
          ulonglong2 v = s2[4 + i];
          X1[2 * i] = v.x; X1[2 * i + 1] = v.y;
        }
      }
      u64 wd[8], pbp[8];
      ldrow8pk(sw->projb + blk * 8, pbp);
      const float* pw = sw->projW + blk * 64;
#pragma unroll
      for (int e = 0; e < 8; e++) {
        ldrow8pk(pw + e * 8, wd);
        X0[e] = add2(X0[e], dot8ri(wd, O0, pbp[e]));
        X1[e] = add2(X1[e], dot8ri(wd, O1, pbp[e]));
      }

      // LN2 core
      u64 H0[8], H1[8];
      cspack(X0, H0);
      cspack(X1, H1);
      // stash X again (dead during MLP)
      {
        ulonglong2* s2 = reinterpret_cast<ulonglong2*>(xs);
#pragma unroll
        for (int i = 0; i < 4; i++)
          s2[i] = make_ulonglong2(X0[2 * i], X0[2 * i + 1]);
#pragma unroll
        for (int i = 0; i < 4; i++)
          s2[4 + i] = make_ulonglong2(X1[2 * i], X1[2 * i + 1]);
      }

      // MLP 8 -> 32 (relu) -> 8; b1e via chain init; acc init = b2
      const float* w1 = sw->W1 + blk * 256;
      const float* b1e = sw->b1e + blk * 32;
      const float* w2 = sw->W2t + blk * 256;
      u64 acc0[8], acc1[8], b2p[8];
      ldrow8pk(sw->b2 + blk * 8, b2p);
#pragma unroll
      for (int d = 0; d < 8; d++) { acc0[d] = b2p[d]; acc1[d] = 0; }
#pragma unroll 4
      for (int f = 0; f < 32; f++) {
        u64 wd2[8];
        ldrow8pk(w1 + f * 8, wd2);
        u64 bf = pk1(b1e[f]);
        u64 f0 = dot8ri(wd2, H0, bf);
        u64 f1 = dot8ri(wd2, H1, bf);
        float fa, fb;
        upk2(f0, fa, fb);
        f0 = pk2(fmaxf(fa, 0.f), fmaxf(fb, 0.f));
        upk2(f1, fa, fb);
        f1 = pk2(fmaxf(fa, 0.f), fmaxf(fb, 0.f));
        ldrow8pk(w2 + f * 8, wd2);
#pragma unroll
        for (int d = 0; d < 8; d++) {
          acc0[d] = fma2(f0, wd2[d], acc0[d]);
          acc1[d] = fma2(f1, wd2[d], acc1[d]);
        }
      }
      // reload X, final residual (b2 already in acc0; add to acc1 via b2p)
      {
        const ulonglong2* s2 = reinterpret_cast<const ulonglong2*>(xs);
#pragma unroll
        for (int i = 0; i < 4; i++) {
          ulonglong2 v = s2[i];
          X0[2 * i] = v.x; X0[2 * i + 1] = v.y;
        }
#pragma unroll
        for (int i = 0; i < 4; i++) {
          ulonglong2 v = s2[4 + i];
          X1[2 * i] = v.x; X1[2 * i + 1] = v.y;
        }
      }
#pragma unroll
      for (int d = 0; d < 8; d++) {
        X0[d] = add2(X0[d], acc0[d]);
        X1[d] = add2(X1[d], add2(acc1[d], b2p[d]));
      }
    }
  }

  // classification head on token 0 (lane 0's t0)
  if (act && lane == 0) {
    float xA[8], xB[8];
#pragma unroll
    for (int d = 0; d < 8; d++) upk2(X0[d], xA[d], xB[d]);
    auto head = [&](const float x[8], int gb) {
      if (gb >= B) return;
      float z[10];
      float zm = -1e30f;
#pragma unroll
      for (int c = 0; c < 10; c++) {
        const float* w = sw->mlpW + c * 8;
        float s = sw->mlpb[c];
#pragma unroll
        for (int j = 0; j < 8; j++) s = fmaf(x[j], w[j], s);
        z[c] = s;
        zm = fmaxf(zm, s);
      }
      float ssum = 0.f;
#pragma unroll
      for (int c = 0; c < 10; c++) { z[c] = __expf(z[c] - zm); ssum += z[c]; }
      float inv = 1.f / ssum;
#pragma unroll
      for (int c = 0; c < 10; c++) out[gb * 10 + c] = z[c] * inv;
    };
    head(xA, gb0);
    head(xB, gb1);
  }
}

extern "C" void kernel_launch(void* const* d_in, const int* in_sizes, int n_in,
                              void* d_out, int out_size) {
  const float* images = (const float*)d_in[0];
  const float* cls    = (const float*)d_in[1];
  const float* linW   = (const float*)d_in[2];
  const float* ln1g   = (const float*)d_in[3];
  const float* ln1b   = (const float*)d_in[4];
  const float* Wq     = (const float*)d_in[5];
  const float* Wk     = (const float*)d_in[6];
  const float* Wv     = (const float*)d_in[7];
  const float* projW  = (const float*)d_in[8];
  const float* projb  = (const float*)d_in[9];
  const float* ln2g   = (const float*)d_in[10];
  const float* ln2b   = (const float*)d_in[11];
  const float* W1     = (const float*)d_in[12];
  const float* b1     = (const float*)d_in[13];
  const float* W2     = (const float*)d_in[14];
  const float* b2     = (const float*)d_in[15];
  const float* mlpW   = (const float*)d_in[16];
  const float* mlpb   = (const float*)d_in[17];

  int B = in_sizes[0] / 784;
  int smem = (KV_U64 + ST_U64) * 8 + (int)sizeof(SW);
  cudaFuncSetAttribute(vit_kernel, cudaFuncAttributeMaxDynamicSharedMemorySize,
                       smem);
  dim3 grid((B + IPC - 1) / IPC);
  vit_kernel<<<grid, NTH, smem>>>(images, cls, linW, ln1g, ln1b, Wq, Wk, Wv,
                                  projW, projb, ln2g, ln2b, W1, b1, W2, b2,
                                  mlpW, mlpb, (float*)d_out, B);
}

// round 15
// speedup vs baseline: 1.0517x; 1.0517x over previous
#include <cuda_runtime.h>

// Tiny-ViT fused forward, round 14: R12 (folds) + three deletions:
//  - stash #2 removed: MLP accumulator initialized from live X (+b2), no
//    store/reload roundtrip at block tail
//  - K/V written as STS.128 pairs (half the store instructions)
//  - rcp.approx for softmax denominators (1 MUFU vs ~8-instr div.rn)
// Retained: LN gain/beta folds into weights/bias-inits, head-split attention,
// 2 tok x 2 img per thread, f32x2 math, base-2 no-max softmax, __syncwarp.
// CTA: 256 threads = 8 warps = 8 slots = 16 images. grid = B/16.

namespace {
constexpr int NB  = 4;
constexpr int TT  = 50;
constexpr int NTH = 256;
constexpr int WPC = 8;
constexpr int IPC = 16;
constexpr int ROW  = 18;   // u64 per kv token row (144B)
constexpr int VOFF = 10;
constexpr int KV_U64 = WPC * TT * ROW;        // 7200
constexpr int ST_STR = 18;
constexpr int ST_U64 = WPC * 25 * ST_STR;     // 3600

struct SW {  // de-duplicated fp32 weights with folded variants
  float Wq[NB * 64], Wk[NB * 64], Wv[NB * 64], projW[NB * 64];  // gains folded
  float W1[NB * 256], W2t[NB * 256];                            // W1: g2 folded
  float qb[NB * 8], kb[NB * 8], vb[NB * 8];   // beta-fold bias vectors
  float b1e[NB * 32];                          // b1 + W1·b2ln
  float projb[NB * 8], b2[NB * 8];
  float linW[128];
  float cls[8];
  float pos[TT * 8];
  float mlpW[80], mlpb[12];
};
}  // namespace

typedef unsigned long long u64;

__device__ __forceinline__ u64 pk2(float a, float b) {
  u64 r;
  asm("mov.b64 %0, {%1, %2};" : "=l"(r)
      : "r"(__float_as_uint(a)), "r"(__float_as_uint(b)));
  return r;
}
__device__ __forceinline__ u64 pk1(float a) {
  u64 r;
  asm("mov.b64 %0, {%1, %1};" : "=l"(r) : "r"(__float_as_uint(a)));
  return r;
}
__device__ __forceinline__ void upk2(u64 v, float& a, float& b) {
  unsigned int x, y;
  asm("mov.b64 {%0, %1}, %2;" : "=r"(x), "=r"(y) : "l"(v));
  a = __uint_as_float(x); b = __uint_as_float(y);
}
__device__ __forceinline__ u64 fma2(u64 a, u64 b, u64 c) {
  u64 d;
  asm("fma.rn.f32x2 %0, %1, %2, %3;" : "=l"(d) : "l"(a), "l"(b), "l"(c));
  return d;
}
__device__ __forceinline__ u64 add2(u64 a, u64 b) {
  u64 d;
  asm("add.rn.f32x2 %0, %1, %2;" : "=l"(d) : "l"(a), "l"(b));
  return d;
}
__device__ __forceinline__ u64 mul2(u64 a, u64 b) {
  u64 d;
  asm("mul.rn.f32x2 %0, %1, %2;" : "=l"(d) : "l"(a), "l"(b));
  return d;
}
__device__ __forceinline__ float ex2f(float x) {
  float r;
  asm("ex2.approx.ftz.f32 %0, %1;" : "=f"(r) : "f"(x));
  return r;
}
__device__ __forceinline__ float rcpf(float x) {
  float r;
  asm("rcp.approx.ftz.f32 %0, %1;" : "=f"(r) : "f"(x));
  return r;
}

// load 8-float row (2x LDS.128 broadcast) and pack to {w,w} dup pairs
__device__ __forceinline__ void ldrow8pk(const float* __restrict__ w, u64 wd[8]) {
  float4 w0 = *reinterpret_cast<const float4*>(w);
  float4 w1 = *reinterpret_cast<const float4*>(w + 4);
  wd[0] = pk1(w0.x); wd[1] = pk1(w0.y); wd[2] = pk1(w0.z); wd[3] = pk1(w0.w);
  wd[4] = pk1(w1.x); wd[5] = pk1(w1.y); wd[6] = pk1(w1.z); wd[7] = pk1(w1.w);
}

// dot8 with chain-init (bias folded in for free)
__device__ __forceinline__ u64 dot8ri(const u64 wd[8], const u64 h[8], u64 init) {
  u64 s0 = fma2(h[0], wd[0], init);
  u64 s1 = mul2(h[1], wd[1]);
  s0 = fma2(h[2], wd[2], s0); s1 = fma2(h[3], wd[3], s1);
  s0 = fma2(h[4], wd[4], s0); s1 = fma2(h[5], wd[5], s1);
  s0 = fma2(h[6], wd[6], s0); s1 = fma2(h[7], wd[7], s1);
  return add2(s0, s1);
}

// centered-scaled LN core: cs = (x - mu) * rsqrt(var + eps)
__device__ __forceinline__ void cspack(const u64 x[8], u64 cs[8]) {
  u64 s = add2(add2(add2(x[0], x[1]), add2(x[2], x[3])),
               add2(add2(x[4], x[5]), add2(x[6], x[7])));
  float sA, sB;
  upk2(s, sA, sB);
  u64 mu = pk2(sA * 0.125f, sB * 0.125f);
  const u64 N1 = pk1(-1.f);
  u64 c[8];
#pragma unroll
  for (int d = 0; d < 8; d++) c[d] = fma2(mu, N1, x[d]);
  u64 v0 = mul2(c[0], c[0]);
  u64 v1 = mul2(c[1], c[1]);
  v0 = fma2(c[2], c[2], v0); v1 = fma2(c[3], c[3], v1);
  v0 = fma2(c[4], c[4], v0); v1 = fma2(c[5], c[5], v1);
  v0 = fma2(c[6], c[6], v0); v1 = fma2(c[7], c[7], v1);
  float vA, vB;
  upk2(add2(v0, v1), vA, vB);
  u64 rs = pk2(rsqrtf(fmaf(vA, 0.125f, 1e-5f)),
               rsqrtf(fmaf(vB, 0.125f, 1e-5f)));
#pragma unroll
  for (int d = 0; d < 8; d++) cs[d] = mul2(c[d], rs);
}

__global__ void __launch_bounds__(NTH, 2) vit_kernel(
    const float* __restrict__ images, const float* __restrict__ cls_g,
    const float* __restrict__ linW_g, const float* __restrict__ ln1g_g,
    const float* __restrict__ ln1b_g, const float* __restrict__ Wq_g,
    const float* __restrict__ Wk_g, const float* __restrict__ Wv_g,
    const float* __restrict__ projW_g, const float* __restrict__ projb_g,
    const float* __restrict__ ln2g_g, const float* __restrict__ ln2b_g,
    const float* __restrict__ W1_g, const float* __restrict__ b1_g,
    const float* __restrict__ W2_g, const float* __restrict__ b2_g,
    const float* __restrict__ mlpW_g, const float* __restrict__ mlpb_g,
    float* __restrict__ out, int B) {
  extern __shared__ __align__(16) char dsm[];
  u64* skv   = reinterpret_cast<u64*>(dsm);
  u64* stash = skv + KV_U64;
  SW* sw = reinterpret_cast<SW*>(reinterpret_cast<char*>(stash + ST_U64));

  const int tid = threadIdx.x;
  const float SCL2E = 0.35355339059327373f * 1.4426950408889634f;

  // ---- stage weights with folds ----
  {
    for (int i = tid; i < NB * 64; i += NTH) {
      int blk = i >> 6, d = i & 7;
      float g1 = ln1g_g[blk * 8 + d];
      sw->Wq[i] = Wq_g[i] * g1 * SCL2E;
      sw->Wk[i] = Wk_g[i] * g1;
      sw->Wv[i] = Wv_g[i] * g1;
      sw->projW[i] = projW_g[i];
    }
    for (int i = tid; i < NB * 256; i += NTH) {
      int blk = i >> 8, d = i & 7;
      sw->W1[i] = W1_g[i] * ln2g_g[blk * 8 + d];
      int rem = i & 255, f = rem >> 3, dd = rem & 7;
      sw->W2t[blk * 256 + rem] = W2_g[blk * 256 + dd * 32 + f];
    }
    for (int i = tid; i < NB * 8; i += NTH) {
      int blk = i >> 3, e = i & 7;
      const float* bb = ln1b_g + blk * 8;
      float sq = 0.f, sk = 0.f, sv = 0.f;
      for (int d = 0; d < 8; d++) {
        float bv = bb[d];
        sq += Wq_g[blk * 64 + e * 8 + d] * bv;
        sk += Wk_g[blk * 64 + e * 8 + d] * bv;
        sv += Wv_g[blk * 64 + e * 8 + d] * bv;
      }
      sw->qb[i] = sq * SCL2E;
      sw->kb[i] = sk;
      sw->vb[i] = sv;
      sw->projb[i] = projb_g[i];
      sw->b2[i] = b2_g[i];
    }
    for (int i = tid; i < NB * 32; i += NTH) {
      int blk = i >> 5, f = i & 31;
      const float* bb = ln2b_g + blk * 8;
      float s = b1_g[i];
      for (int d = 0; d < 8; d++) s += W1_g[blk * 256 + f * 8 + d] * bb[d];
      sw->b1e[i] = s;
    }
    auto cp = [&](float* d, const float* s, int n) {
      for (int i = tid; i < n; i += NTH) d[i] = s[i];
    };
    cp(sw->linW, linW_g, 128);
    cp(sw->cls, cls_g, 8);
    cp(sw->mlpW, mlpW_g, 80);
    for (int i = tid; i < 10; i += NTH) sw->mlpb[i] = mlpb_g[i];
    if (tid < TT) {  // sinusoidal table: freqs {1, .1, .01, .001}
      float tf = (float)tid;
      float* p = sw->pos + tid * 8;
      p[0] = sinf(tf);          p[1] = cosf(tf);
      p[2] = sinf(tf * 0.1f);   p[3] = cosf(tf * 0.1f);
      p[4] = sinf(tf * 0.01f);  p[5] = cosf(tf * 0.01f);
      p[6] = sinf(tf * 0.001f); p[7] = cosf(tf * 0.001f);
    }
  }
  __syncthreads();  // CTA-wide: weights staged cooperatively

  const int warp = tid >> 5;
  const int lane = tid & 31;
  const bool act = (lane < 25);
  const int t0 = lane;
  const int t1 = lane + 25;
  const int gb0 = (blockIdx.x * WPC + warp) * 2;
  const int gb1 = gb0 + 1;

  u64* kvb = skv + warp * (TT * ROW);
  u64* xs  = stash + (warp * 25 + lane) * ST_STR;

  u64 X0[8], X1[8];

  // ---- patch embed + positional ----
  if (act) {
    auto embed_tok = [&](int t, u64 xr[8]) {
      if (t == 0) {
#pragma unroll
        for (int d = 0; d < 8; d++) {
          float v = sw->cls[d] + sw->pos[d];
          xr[d] = pk1(v);
        }
        return;
      }
      int p = t - 1, r = p / 7, c = p % 7;
      float eo[2][8];
#pragma unroll
      for (int img = 0; img < 2; img++) {
        int gb = gb0 + img;
        float px[16];
        if (gb < B) {
          const float* ip = images + (size_t)gb * 784 + (r * 4) * 28 + c * 4;
#pragma unroll
          for (int i = 0; i < 4; i++) {
            float4 v4 = *reinterpret_cast<const float4*>(ip + i * 28);
            px[4 * i] = v4.x; px[4 * i + 1] = v4.y;
            px[4 * i + 2] = v4.z; px[4 * i + 3] = v4.w;
          }
        } else {
#pragma unroll
          for (int j = 0; j < 16; j++) px[j] = 0.f;
        }
#pragma unroll
        for (int d = 0; d < 8; d++) {
          const float* w = sw->linW + d * 16;
          float s = 0.f;
#pragma unroll
          for (int j = 0; j < 16; j++) s = fmaf(px[j], w[j], s);
          eo[img][d] = s + sw->pos[t * 8 + d];
        }
      }
#pragma unroll
      for (int d = 0; d < 8; d++) xr[d] = pk2(eo[0][d], eo[1][d]);
    };
    embed_tok(t0, X0);
    embed_tok(t1, X1);
  }

#pragma unroll 1
  for (int blk = 0; blk < NB; blk++) {
    u64 Q0[8], Q1[8];
    if (act) {
      // LN1 core (gains/betas folded downstream)
      u64 H0[8], H1[8];
      cspack(X0, H0);
      cspack(X1, H1);
      // stash X (dead until proj residual)
      {
        ulonglong2* s2 = reinterpret_cast<ulonglong2*>(xs);
#pragma unroll
        for (int i = 0; i < 4; i++)
          s2[i] = make_ulonglong2(X0[2 * i], X0[2 * i + 1]);
#pragma unroll
        for (int i = 0; i < 4; i++)
          s2[4 + i] = make_ulonglong2(X1[2 * i], X1[2 * i + 1]);
      }
      u64 wd[8], bp[8];
      const float* wq = sw->Wq + blk * 64;
      ldrow8pk(sw->qb + blk * 8, bp);
#pragma unroll
      for (int e = 0; e < 8; e++) {
        ldrow8pk(wq + e * 8, wd);
        Q0[e] = dot8ri(wd, H0, bp[e]);
        Q1[e] = dot8ri(wd, H1, bp[e]);
      }
      // K: compute e-pairs, store as STS.128
      const float* wk = sw->Wk + blk * 64;
      ldrow8pk(sw->kb + blk * 8, bp);
      ulonglong2* kp0 = reinterpret_cast<ulonglong2*>(kvb + t0 * ROW);
      ulonglong2* kp1 = reinterpret_cast<ulonglong2*>(kvb + t1 * ROW);
#pragma unroll
      for (int ep = 0; ep < 4; ep++) {
        u64 wdb[8];
        ldrow8pk(wk + (2 * ep) * 8, wd);
        ldrow8pk(wk + (2 * ep + 1) * 8, wdb);
        kp0[ep] = make_ulonglong2(dot8ri(wd, H0, bp[2 * ep]),
                                  dot8ri(wdb, H0, bp[2 * ep + 1]));
        kp1[ep] = make_ulonglong2(dot8ri(wd, H1, bp[2 * ep]),
                                  dot8ri(wdb, H1, bp[2 * ep + 1]));
      }
      // V: same, at VOFF (80B, 16B-aligned)
      const float* wv = sw->Wv + blk * 64;
      ldrow8pk(sw->vb + blk * 8, bp);
      ulonglong2* vp0 = reinterpret_cast<ulonglong2*>(kvb + t0 * ROW + VOFF);
      ulonglong2* vp1 = reinterpret_cast<ulonglong2*>(kvb + t1 * ROW + VOFF);
#pragma unroll
      for (int ep = 0; ep < 4; ep++) {
        u64 wdb[8];
        ldrow8pk(wv + (2 * ep) * 8, wd);
        ldrow8pk(wv + (2 * ep + 1) * 8, wdb);
        vp0[ep] = make_ulonglong2(dot8ri(wd, H0, bp[2 * ep]),
                                  dot8ri(wdb, H0, bp[2 * ep + 1]));
        vp1[ep] = make_ulonglong2(dot8ri(wd, H1, bp[2 * ep]),
                                  dot8ri(wdb, H1, bp[2 * ep + 1]));
      }
    }
    __syncwarp();  // K/V warp-private

    u64 O0[8], O1[8];
    if (act) {
      // base-2 no-max softmax, two sequential per-head passes
#pragma unroll 1
      for (int h = 0; h < 2; h++) {
        const u64 q00 = Q0[4 * h + 0], q01 = Q0[4 * h + 1];
        const u64 q02 = Q0[4 * h + 2], q03 = Q0[4 * h + 3];
        const u64 q10 = Q1[4 * h + 0], q11 = Q1[4 * h + 1];
        const u64 q12 = Q1[4 * h + 2], q13 = Q1[4 * h + 3];
        const u64* kh = kvb + 4 * h;
        const u64* vh = kvb + VOFF + 4 * h;
        u64 l0 = 0, l1 = 0;
        u64 a00 = 0, a01 = 0, a02 = 0, a03 = 0;
        u64 a10 = 0, a11 = 0, a12 = 0, a13 = 0;
#pragma unroll 2
        for (int u = 0; u < TT; u++) {
          const ulonglong2* kp =
              reinterpret_cast<const ulonglong2*>(kh + u * ROW);
          ulonglong2 k0 = kp[0], k1 = kp[1];
          const ulonglong2* vp =
              reinterpret_cast<const ulonglong2*>(vh + u * ROW);
          ulonglong2 v0 = vp[0], v1 = vp[1];
          u64 s0 = fma2(q00, k0.x,
                   fma2(q01, k0.y, fma2(q02, k1.x, mul2(q03, k1.y))));
          u64 s1 = fma2(q10, k0.x,
                   fma2(q11, k0.y, fma2(q12, k1.x, mul2(q13, k1.y))));
          float xa, xb;
          upk2(s0, xa, xb);
          u64 p0 = pk2(ex2f(xa), ex2f(xb));
          upk2(s1, xa, xb);
          u64 p1 = pk2(ex2f(xa), ex2f(xb));
          l0 = add2(l0, p0);
          l1 = add2(l1, p1);
          a00 = fma2(p0, v0.x, a00); a01 = fma2(p0, v0.y, a01);
          a02 = fma2(p0, v1.x, a02); a03 = fma2(p0, v1.y, a03);
          a10 = fma2(p1, v0.x, a10); a11 = fma2(p1, v0.y, a11);
          a12 = fma2(p1, v1.x, a12); a13 = fma2(p1, v1.y, a13);
        }
        float lA, lB;
        upk2(l0, lA, lB);
        u64 i0 = pk2(rcpf(lA), rcpf(lB));
        upk2(l1, lA, lB);
        u64 i1 = pk2(rcpf(lA), rcpf(lB));
        O0[4 * h + 0] = mul2(a00, i0); O0[4 * h + 1] = mul2(a01, i0);
        O0[4 * h + 2] = mul2(a02, i0); O0[4 * h + 3] = mul2(a03, i0);
        O1[4 * h + 0] = mul2(a10, i1); O1[4 * h + 1] = mul2(a11, i1);
        O1[4 * h + 2] = mul2(a12, i1); O1[4 * h + 3] = mul2(a13, i1);
      }
    }
    __syncwarp();  // kv consumed

    if (act) {
      // reload X, proj + residual (proj bias via chain init)
      {
        const ulonglong2* s2 = reinterpret_cast<const ulonglong2*>(xs);
#pragma unroll
        for (int i = 0; i < 4; i++) {
          ulonglong2 v = s2[i];
          X0[2 * i] = v.x; X0[2 * i + 1] = v.y;
        }
#pragma unroll
        for (int i = 0; i < 4; i++) {
          ulonglong2 v = s2[4 + i];
          X1[2 * i] = v.x; X1[2 * i + 1] = v.y;
        }
      }
      u64 wd[8], pbp[8];
      ldrow8pk(sw->projb + blk * 8, pbp);
      const float* pw = sw->projW + blk * 64;
#pragma unroll
      for (int e = 0; e < 8; e++) {
        ldrow8pk(pw + e * 8, wd);
        X0[e] = add2(X0[e], dot8ri(wd, O0, pbp[e]));
        X1[e] = add2(X1[e], dot8ri(wd, O1, pbp[e]));
      }

      // LN2 core (X stays LIVE — no stash: acc carries X through the MLP)
      u64 H0[8], H1[8];
      cspack(X0, H0);
      cspack(X1, H1);

      // MLP 8 -> 32 (relu) -> 8; acc initialized as X + b2
      const float* w1 = sw->W1 + blk * 256;
      const float* b1e = sw->b1e + blk * 32;
      const float* w2 = sw->W2t + blk * 256;
      u64 acc0[8], acc1[8], b2p[8];
      ldrow8pk(sw->b2 + blk * 8, b2p);
#pragma unroll
      for (int d = 0; d < 8; d++) {
        acc0[d] = add2(X0[d], b2p[d]);
        acc1[d] = add2(X1[d], b2p[d]);
      }
#pragma unroll 4
      for (int f = 0; f < 32; f++) {
        u64 wd2[8];
        ldrow8pk(w1 + f * 8, wd2);
        u64 bf = pk1(b1e[f]);
        u64 f0 = dot8ri(wd2, H0, bf);
        u64 f1 = dot8ri(wd2, H1, bf);
        float fa, fb;
        upk2(f0, fa, fb);
        f0 = pk2(fmaxf(fa, 0.f), fmaxf(fb, 0.f));
        upk2(f1, fa, fb);
        f1 = pk2(fmaxf(fa, 0.f), fmaxf(fb, 0.f));
        ldrow8pk(w2 + f * 8, wd2);
#pragma unroll
        for (int d = 0; d < 8; d++) {
          acc0[d] = fma2(f0, wd2[d], acc0[d]);
          acc1[d] = fma2(f1, wd2[d], acc1[d]);
        }
      }
      // acc IS the new X (residual + MLP + b2 all included)
#pragma unroll
      for (int d = 0; d < 8; d++) {
        X0[d] = acc0[d];
        X1[d] = acc1[d];
      }
    }
  }

  // classification head on token 0 (lane 0's t0)
  if (act && lane == 0) {
    float xA[8], xB[8];
#pragma unroll
    for (int d = 0; d < 8; d++) upk2(X0[d], xA[d], xB[d]);
    auto head = [&](const float x[8], int gb) {
      if (gb >= B) return;
      float z[10];
      float zm = -1e30f;
#pragma unroll
      for (int c = 0; c < 10; c++) {
        const float* w = sw->mlpW + c * 8;
        float s = sw->mlpb[c];
#pragma unroll
        for (int j = 0; j < 8; j++) s = fmaf(x[j], w[j], s);
        z[c] = s;
        zm = fmaxf(zm, s);
      }
      float ssum = 0.f;
#pragma unroll
      for (int c = 0; c < 10; c++) { z[c] = __expf(z[c] - zm); ssum += z[c]; }
      float inv = rcpf(ssum);
#pragma unroll
      for (int c = 0; c < 10; c++) out[gb * 10 + c] = z[c] * inv;
    };
    head(xA, gb0);
    head(xB, gb1);
  }
}

extern "C" void kernel_launch(void* const* d_in, const int* in_sizes, int n_in,
                              void* d_out, int out_size) {
  const float* images = (const float*)d_in[0];
  const float* cls    = (const float*)d_in[1];
  const float* linW   = (const float*)d_in[2];
  const float* ln1g   = (const float*)d_in[3];
  const float* ln1b   = (const float*)d_in[4];
  const float* Wq     = (const float*)d_in[5];
  const float* Wk     = (const float*)d_in[6];
  const float* Wv     = (const float*)d_in[7];
  const float* projW  = (const float*)d_in[8];
  const float* projb  = (const float*)d_in[9];
  const float* ln2g   = (const float*)d_in[10];
  const float* ln2b   = (const float*)d_in[11];
  const float* W1     = (const float*)d_in[12];
  const float* b1     = (const float*)d_in[13];
  const float* W2     = (const float*)d_in[14];
  const float* b2     = (const float*)d_in[15];
  const float* mlpW   = (const float*)d_in[16];
  const float* mlpb   = (const float*)d_in[17];

  int B = in_sizes[0] / 784;
  int smem = (KV_U64 + ST_U64) * 8 + (int)sizeof(SW);
  cudaFuncSetAttribute(vit_kernel, cudaFuncAttributeMaxDynamicSharedMemorySize,
                       smem);
  dim3 grid((B + IPC - 1) / IPC);
  vit_kernel<<<grid, NTH, smem>>>(images, cls, linW, ln1g, ln1b, Wq, Wk, Wv,
                                  projW, projb, ln2g, ln2b, W1, b1, W2, b2,
                                  mlpW, mlpb, (float*)d_out, B);
}